// round 16
// baseline (speedup 1.0000x reference)
#include <cuda_runtime.h>
#include <cuda_bf16.h>
#include <cuda_fp16.h>
#include <cstdint>

#define N_NODES 100000
#define N_EDGES 1600000
#define N_PAIRS 200000
#define CH 128

typedef unsigned int u32;
typedef unsigned long long u64;

// ---------------- scratch (static device globals; no allocation) -------------
__device__ int   g_cnt[N_NODES];
__device__ int   g_rowptr[N_NODES + 1];
__device__ int   g_cursor[N_NODES];
__device__ int2  g_csr[N_EDGES];

__device__ __align__(16) __half g_x16[(size_t)N_NODES * CH];  // 25.6 MB
__device__ __align__(16) __half g_h16[(size_t)N_NODES * CH];  // 25.6 MB
__device__ __align__(16) __half g_a16[(size_t)N_NODES * CH];  // 25.6 MB (agg, fp16)
__device__ float g_z[(size_t)N_NODES * CH];                   // 51.2 MB fp32
// weight image: 2 layers x 4 k-chunks x 2 planes x 16KB (swizzled) = 256 KB
__device__ __align__(16) u32 g_Bimg[65536];

// ---------------- PTX helpers (all plain sm_80+ ISA) -------------------------
__device__ __forceinline__ u32 smem_u32(const void* p) {
    u32 a;
    asm("{ .reg .u64 t; cvta.to.shared.u64 t, %1; cvt.u32.u64 %0, t; }" : "=r"(a) : "l"(p));
    return a;
}

__device__ __forceinline__ void ldsm_x4(u32& r0, u32& r1, u32& r2, u32& r3, u32 addr) {
    asm volatile("ldmatrix.sync.aligned.m8n8.x4.shared.b16 {%0,%1,%2,%3}, [%4];"
                 : "=r"(r0), "=r"(r1), "=r"(r2), "=r"(r3) : "r"(addr));
}

__device__ __forceinline__ void mma_bf16(float* c, const u32* a, const u32* b) {
    asm volatile(
        "mma.sync.aligned.m16n8k16.row.col.f32.bf16.bf16.f32 "
        "{%0,%1,%2,%3}, {%4,%5,%6,%7}, {%8,%9}, {%0,%1,%2,%3};"
        : "+f"(c[0]), "+f"(c[1]), "+f"(c[2]), "+f"(c[3])
        : "r"(a[0]), "r"(a[1]), "r"(a[2]), "r"(a[3]), "r"(b[0]), "r"(b[1]));
}

__device__ __forceinline__ void cpa16(u32 dst, const void* src, bool pred) {
    int sz = pred ? 16 : 0;
    asm volatile("cp.async.cg.shared.global [%0], [%1], 16, %2;"
                 :: "r"(dst), "l"(src), "r"(sz) : "memory");
}
#define CPA_COMMIT()  asm volatile("cp.async.commit_group;" ::: "memory")
#define CPA_WAIT(n)   asm volatile("cp.async.wait_group %0;" :: "n"(n) : "memory")

// bf16 split helpers
__device__ __forceinline__ u32 pack_bf2(float a, float b) {
    __nv_bfloat16 x = __float2bfloat16_rn(a);
    __nv_bfloat16 y = __float2bfloat16_rn(b);
    return (u32)__bfloat16_as_ushort(x) | ((u32)__bfloat16_as_ushort(y) << 16);
}
__device__ __forceinline__ float bf_hi(float v) {
    return __bfloat162float(__float2bfloat16_rn(v));
}
// fp16 pack/unpack
__device__ __forceinline__ u32 pack_h2(float a, float b) {
    __half2 h = __floats2half2_rn(a, b);
    return *reinterpret_cast<u32*>(&h);
}
__device__ __forceinline__ float2 unp_h2(u32 v) {
    __half2 h = *reinterpret_cast<__half2*>(&v);
    return __half22float2(h);
}

// ---------------- CSR build --------------------------------------------------
__global__ void k_zero() {
    int i = blockIdx.x * blockDim.x + threadIdx.x;
    if (i < N_NODES) g_cnt[i] = 0;
}

// fused: edge-dst histogram + x -> fp16 (both exactly 1.6M threads)
__global__ void k_hist_cvt(const int* __restrict__ ei, const float* __restrict__ x) {
    int gid = blockIdx.x * blockDim.x + threadIdx.x;
    if (gid >= N_EDGES) return;
    atomicAdd(&g_cnt[ei[N_EDGES + gid]], 1);
    // convert 8 channels: N_EDGES == N_NODES*16 exactly
    const float4* x4 = reinterpret_cast<const float4*>(x);
    float4 a = x4[gid * 2];
    float4 b = x4[gid * 2 + 1];
    uint4 o = make_uint4(pack_h2(a.x, a.y), pack_h2(a.z, a.w),
                         pack_h2(b.x, b.y), pack_h2(b.z, b.w));
    reinterpret_cast<uint4*>(g_x16)[gid] = o;
}

__global__ void k_scan() {
    __shared__ int sm[1024];
    const int CHUNK = (N_NODES + 1023) / 1024;
    int t = threadIdx.x;
    int beg = t * CHUNK;
    int end = beg + CHUNK; if (end > N_NODES) end = N_NODES;
    int s = 0;
    for (int i = beg; i < end && i < N_NODES; i++) s += g_cnt[i];
    sm[t] = s;
    __syncthreads();
    for (int off = 1; off < 1024; off <<= 1) {
        int v = (t >= off) ? sm[t - off] : 0;
        __syncthreads();
        sm[t] += v;
        __syncthreads();
    }
    int run = sm[t] - s;
    for (int i = beg; i < end && i < N_NODES; i++) {
        int c = g_cnt[i];
        g_rowptr[i] = run;
        g_cursor[i] = run;
        run += c;
    }
    if (t == 1023) g_rowptr[N_NODES] = sm[1023];
}

// fused: CSR scatter (all 1.6M threads) + weight split/swizzle (first 64K)
__global__ void k_scatter_prep(const int* __restrict__ ei, const float* __restrict__ ew,
                               const float* __restrict__ w1_rel, const float* __restrict__ w1_root,
                               const float* __restrict__ w2_rel, const float* __restrict__ w2_root) {
    int e = blockIdx.x * blockDim.x + threadIdx.x;
    if (e < N_EDGES) {
        int d = ei[N_EDGES + e];
        int p = atomicAdd(&g_cursor[d], 1);
        g_csr[p] = make_int2(ei[e], __float_as_int(ew[e]));
    }
    if (e < 65536) {
        int l = e >> 15;
        int r = e & 32767;
        int k = r >> 7;          // 0..255
        int n = r & 127;
        const float* W = (k < 128) ? (l ? w2_rel : w1_rel) : (l ? w2_root : w1_root);
        float v = W[(k & 127) * 128 + n];   // B[n][k] = W[k][n]
        float h = bf_hi(v);
        float lo = v - h;
        int c  = k >> 6;
        int kk = k & 63;
        int u  = kk >> 3;
        int bi = (kk & 7) * 2;
        u32 phys = (u32)n * 128u + (u32)(((u ^ (n & 7)) << 4) | bi);
        u32 base = (u32)((l * 4 + c) * 2) * 16384u;
        unsigned short* B = reinterpret_cast<unsigned short*>(g_Bimg);
        B[(base + phys) >> 1]           = __bfloat16_as_ushort(__float2bfloat16_rn(h));
        B[(base + 16384u + phys) >> 1]  = __bfloat16_as_ushort(__float2bfloat16_rn(lo));
    }
}

// ---------------- gather-side mean aggregation (fp16 gather, fp32 accum) -----
// warp per node (no intra-warp degree divergence), uint2 per lane.
// 8-edge unrolled main loop: 8 independent feature-row gathers in flight per
// warp (double the MLP of the 4-unroll) + one coalesced 64B CSR run.
__global__ void k_agg(int use_h) {
    int gid  = blockIdx.x * blockDim.x + threadIdx.x;
    int node = gid >> 5;
    if (node >= N_NODES) return;
    int lane = gid & 31;
    const uint2* feat = reinterpret_cast<const uint2*>(use_h ? g_h16 : g_x16);

    int beg = g_rowptr[node];
    int end = g_rowptr[node + 1];

    float ax = 0.f, ay = 0.f, az = 0.f, aw = 0.f;

    #define AGG_ONE(cc, vv)                                         \
    {                                                               \
        float w = __int_as_float((cc).y);                           \
        float2 p0 = unp_h2((vv).x), p1 = unp_h2((vv).y);            \
        ax = fmaf(w, p0.x, ax); ay = fmaf(w, p0.y, ay);             \
        az = fmaf(w, p1.x, az); aw = fmaf(w, p1.y, aw);             \
    }

    int e = beg;
    #pragma unroll 1
    for (; e + 8 <= end; e += 8) {
        int2 c0 = __ldg(&g_csr[e]);
        int2 c1 = __ldg(&g_csr[e + 1]);
        int2 c2 = __ldg(&g_csr[e + 2]);
        int2 c3 = __ldg(&g_csr[e + 3]);
        int2 c4 = __ldg(&g_csr[e + 4]);
        int2 c5 = __ldg(&g_csr[e + 5]);
        int2 c6 = __ldg(&g_csr[e + 6]);
        int2 c7 = __ldg(&g_csr[e + 7]);
        uint2 v0 = __ldg(feat + (size_t)c0.x * 32 + lane);
        uint2 v1 = __ldg(feat + (size_t)c1.x * 32 + lane);
        uint2 v2 = __ldg(feat + (size_t)c2.x * 32 + lane);
        uint2 v3 = __ldg(feat + (size_t)c3.x * 32 + lane);
        uint2 v4 = __ldg(feat + (size_t)c4.x * 32 + lane);
        uint2 v5 = __ldg(feat + (size_t)c5.x * 32 + lane);
        uint2 v6 = __ldg(feat + (size_t)c6.x * 32 + lane);
        uint2 v7 = __ldg(feat + (size_t)c7.x * 32 + lane);
        AGG_ONE(c0, v0); AGG_ONE(c1, v1); AGG_ONE(c2, v2); AGG_ONE(c3, v3);
        AGG_ONE(c4, v4); AGG_ONE(c5, v5); AGG_ONE(c6, v6); AGG_ONE(c7, v7);
    }
    #pragma unroll 1
    for (; e + 4 <= end; e += 4) {
        int2 c0 = __ldg(&g_csr[e]);
        int2 c1 = __ldg(&g_csr[e + 1]);
        int2 c2 = __ldg(&g_csr[e + 2]);
        int2 c3 = __ldg(&g_csr[e + 3]);
        uint2 v0 = __ldg(feat + (size_t)c0.x * 32 + lane);
        uint2 v1 = __ldg(feat + (size_t)c1.x * 32 + lane);
        uint2 v2 = __ldg(feat + (size_t)c2.x * 32 + lane);
        uint2 v3 = __ldg(feat + (size_t)c3.x * 32 + lane);
        AGG_ONE(c0, v0); AGG_ONE(c1, v1); AGG_ONE(c2, v2); AGG_ONE(c3, v3);
    }
    #pragma unroll 1
    for (; e < end; e++) {
        int2 c0 = __ldg(&g_csr[e]);
        uint2 v0 = __ldg(feat + (size_t)c0.x * 32 + lane);
        AGG_ONE(c0, v0);
    }
    #undef AGG_ONE

    float inv = 1.0f / fmaxf((float)(end - beg), 1.0f);
    uint2 o = make_uint2(pack_h2(ax * inv, ay * inv), pack_h2(az * inv, aw * inv));
    reinterpret_cast<uint2*>(g_a16)[(size_t)node * 32 + lane] = o;
}

// ---------------- mma.sync bf16-split GEMM -----------------------------------
// out[m,0:128] = act([agg | other][m,0:256] @ W[256,128] + bias)
// A is fp16 everywhere (agg, x, h); fp16 -> bf16 hi+lo split is exact.
// smem: A hi 16K | A lo 16K | B hi 16K | B lo 16K = 64 KB;
// fp32 stage (128x132 = 67.6 KB) overlays it after compute. 2 CTAs/SM.
#define GM_SMEM 67584

__global__ __launch_bounds__(256, 2) void k_gemm_mma(const float* __restrict__ bias, int layer)
{
    extern __shared__ char smem[];
    const u32 sb = smem_u32(smem);
    const int tid  = threadIdx.x;
    const int lane = tid & 31;
    const int wid  = tid >> 5;
    const int m0   = blockIdx.x * 128;

    const uint4* agg16   = reinterpret_cast<const uint4*>(g_a16);
    const uint4* other16 = reinterpret_cast<const uint4*>(layer ? g_h16 : g_x16);
    const uint4* Bimg = reinterpret_cast<const uint4*>(g_Bimg) + (size_t)layer * 8192;

    const int mbase = (wid >> 2) * 64;
    const int ntb   = (wid & 3) * 4;        // n-tile base (n8 units)

    float acc[4][4][4];
    #pragma unroll
    for (int a = 0; a < 4; a++)
        #pragma unroll
        for (int b = 0; b < 4; b++)
            #pragma unroll
            for (int d = 0; d < 4; d++) acc[a][b][d] = 0.f;

    #pragma unroll 1
    for (int c = 0; c < 4; c++) {
        // ---- B planes via cp.async (pre-split, pre-swizzled) ----
        const uint4* bsrc = Bimg + (size_t)c * 2048;   // 32 KB (hi|lo)
        #pragma unroll
        for (int i = 0; i < 8; i++) {
            int e = i * 256 + tid;
            cpa16(sb + 32768u + (u32)e * 16u, bsrc + e, true);
        }
        CPA_COMMIT();

        // ---- A: load fp16, split hi/lo in regs, store swizzled ----
        {
            int half = c & 1;               // K cols [half*64, half*64+64)
            const uint4* src = (c >> 1) ? other16 : agg16;
            #pragma unroll
            for (int i = 0; i < 4; i++) {
                int t = i * 256 + tid;      // 0..1023 : 128 rows x 8 units
                int r = t >> 3, u = t & 7;
                int gm = m0 + r;
                float f[8] = {0.f, 0.f, 0.f, 0.f, 0.f, 0.f, 0.f, 0.f};
                if (gm < N_NODES) {
                    uint4 raw = __ldg(src + (size_t)gm * 16 + half * 8 + u);
                    float2 p0 = unp_h2(raw.x), p1 = unp_h2(raw.y);
                    float2 p2 = unp_h2(raw.z), p3 = unp_h2(raw.w);
                    f[0] = p0.x; f[1] = p0.y; f[2] = p1.x; f[3] = p1.y;
                    f[4] = p2.x; f[5] = p2.y; f[6] = p3.x; f[7] = p3.y;
                }
                float h0 = bf_hi(f[0]), h1 = bf_hi(f[1]), h2 = bf_hi(f[2]), h3 = bf_hi(f[3]);
                float h4 = bf_hi(f[4]), h5 = bf_hi(f[5]), h6 = bf_hi(f[6]), h7 = bf_hi(f[7]);
                uint4 hi = make_uint4(pack_bf2(h0, h1), pack_bf2(h2, h3),
                                      pack_bf2(h4, h5), pack_bf2(h6, h7));
                uint4 lo = make_uint4(pack_bf2(f[0] - h0, f[1] - h1),
                                      pack_bf2(f[2] - h2, f[3] - h3),
                                      pack_bf2(f[4] - h4, f[5] - h5),
                                      pack_bf2(f[6] - h6, f[7] - h7));
                u32 off = (u32)(r * 128 + ((u ^ (r & 7)) << 4));
                *reinterpret_cast<uint4*>(smem + off)          = hi;
                *reinterpret_cast<uint4*>(smem + 16384u + off) = lo;
            }
        }

        CPA_WAIT(0);
        __syncthreads();

        #pragma unroll
        for (int ks = 0; ks < 4; ks++) {
            u32 ah[4][4], al[4][4], bh[4][2], bl[4][2];
            #pragma unroll
            for (int mt = 0; mt < 4; mt++) {
                int row = mbase + mt * 16 + (lane & 15);
                int u   = 2 * ks + (lane >> 4);
                u32 off = (u32)(row * 128 + ((u ^ (row & 7)) << 4));
                ldsm_x4(ah[mt][0], ah[mt][1], ah[mt][2], ah[mt][3], sb + off);
                ldsm_x4(al[mt][0], al[mt][1], al[mt][2], al[mt][3], sb + 16384u + off);
            }
            #pragma unroll
            for (int pr = 0; pr < 2; pr++) {
                int g  = lane >> 3;
                int nt = ntb + pr * 2 + (g >> 1);
                int rn = nt * 8 + (lane & 7);
                int u  = 2 * ks + (g & 1);
                u32 off = (u32)(rn * 128 + ((u ^ (rn & 7)) << 4));
                ldsm_x4(bh[pr*2][0], bh[pr*2][1], bh[pr*2+1][0], bh[pr*2+1][1], sb + 32768u + off);
                ldsm_x4(bl[pr*2][0], bl[pr*2][1], bl[pr*2+1][0], bl[pr*2+1][1], sb + 49152u + off);
            }
            #pragma unroll
            for (int mt = 0; mt < 4; mt++)
                #pragma unroll
                for (int nt = 0; nt < 4; nt++) {
                    mma_bf16(acc[mt][nt], ah[mt], bh[nt]);
                    mma_bf16(acc[mt][nt], ah[mt], bl[nt]);
                    mma_bf16(acc[mt][nt], al[mt], bh[nt]);
                }
        }
        __syncthreads();
    }

    // ---- stage accumulators to smem (overlays buffers) ----
    float* stage = reinterpret_cast<float*>(smem);
    #pragma unroll
    for (int mt = 0; mt < 4; mt++)
        #pragma unroll
        for (int nt = 0; nt < 4; nt++) {
            int row = mbase + mt * 16 + (lane >> 2);
            int col = (wid & 3) * 32 + nt * 8 + (lane & 3) * 2;
            stage[row * 132 + col]           = acc[mt][nt][0];
            stage[row * 132 + col + 1]       = acc[mt][nt][1];
            stage[(row + 8) * 132 + col]     = acc[mt][nt][2];
            stage[(row + 8) * 132 + col + 1] = acc[mt][nt][3];
        }
    __syncthreads();

    // ---- bias / act / store ----
    if (layer == 0) {
        // h -> fp16 (+ReLU), packed half2 stores
        u32* oh = reinterpret_cast<u32*>(g_h16);
        #pragma unroll 4
        for (int i = 0; i < 32; i++) {
            int p = i * 256 + tid;          // pair index: 8192 pairs
            int m = p >> 6, c2 = (p & 63) * 2;
            int gm = m0 + m;
            if (gm >= N_NODES) continue;
            float v0 = stage[m * 132 + c2]     + __ldg(&bias[c2]);
            float v1 = stage[m * 132 + c2 + 1] + __ldg(&bias[c2 + 1]);
            v0 = fmaxf(v0, 0.f);
            v1 = fmaxf(v1, 0.f);
            oh[(size_t)gm * 64 + (c2 >> 1)] = pack_h2(v0, v1);
        }
    } else {
        #pragma unroll 4
        for (int i = 0; i < 64; i++) {
            int p = i * 256 + tid;          // element index: 16384
            int m = p >> 7, cc = p & 127;
            int gm = m0 + m;
            if (gm >= N_NODES) continue;
            g_z[(size_t)gm * CH + cc] = stage[m * 132 + cc] + __ldg(&bias[cc]);
        }
    }
}

// ---------------- decode: warp per candidate pair (fp32 z) -------------------
__global__ void k_decode(const int* __restrict__ eli, float* __restrict__ out) {
    int gid = blockIdx.x * blockDim.x + threadIdx.x;
    int p = gid >> 5;
    if (p >= N_PAIRS) return;
    int lane = gid & 31;
    int a = eli[p];
    int b = eli[N_PAIRS + p];
    float4 va = *reinterpret_cast<const float4*>(&g_z[(size_t)a * CH + lane * 4]);
    float4 vb = *reinterpret_cast<const float4*>(&g_z[(size_t)b * CH + lane * 4]);
    float s = va.x * vb.x + va.y * vb.y + va.z * vb.z + va.w * vb.w;
    #pragma unroll
    for (int off = 16; off > 0; off >>= 1) s += __shfl_xor_sync(0xFFFFFFFFu, s, off);
    if (lane == 0) out[p] = s * 0.08838834764831845f;   // 1/sqrt(128)
}

// ---------------- launch -----------------------------------------------------
extern "C" void kernel_launch(void* const* d_in, const int* in_sizes, int n_in,
                              void* d_out, int out_size) {
    const float* x       = (const float*)d_in[0];
    const int*   ei      = (const int*)  d_in[1];
    const float* ew      = (const float*)d_in[2];
    const int*   eli     = (const int*)  d_in[3];
    const float* w1_rel  = (const float*)d_in[4];
    const float* b1      = (const float*)d_in[5];
    const float* w1_root = (const float*)d_in[6];
    const float* w2_rel  = (const float*)d_in[7];
    const float* b2      = (const float*)d_in[8];
    const float* w2_root = (const float*)d_in[9];
    float* out = (float*)d_out;

    cudaFuncSetAttribute(k_gemm_mma, cudaFuncAttributeMaxDynamicSharedMemorySize, GM_SMEM);

    // CSR build + operand prep (x->fp16 fused with hist, weights with scatter)
    k_zero        <<<(N_NODES + 255) / 256, 256>>>();
    k_hist_cvt    <<<(N_EDGES + 255) / 256, 256>>>(ei, x);
    k_scan        <<<1, 1024>>>();
    k_scatter_prep<<<(N_EDGES + 255) / 256, 256>>>(ei, ew, w1_rel, w1_root, w2_rel, w2_root);

    const int aggBlocks  = (N_NODES * 32 + 255) / 256;
    const int gemmBlocks = (N_NODES + 127) / 128;

    // layer 1: h = relu([agg(x) | x] @ [W1_rel; W1_root] + b1)  (fp16 h)
    k_agg     <<<aggBlocks, 256>>>(0);
    k_gemm_mma<<<gemmBlocks, 256, GM_SMEM>>>(b1, 0);

    // layer 2: z = [agg(h) | h] @ [W2_rel; W2_root] + b2  (fp32 z)
    k_agg     <<<aggBlocks, 256>>>(1);
    k_gemm_mma<<<gemmBlocks, 256, GM_SMEM>>>(b2, 1);

    // decode
    k_decode<<<(N_PAIRS * 32 + 255) / 256, 256>>>(eli, out);
}

// round 17
// speedup vs baseline: 1.2354x; 1.2354x over previous
#include <cuda_runtime.h>
#include <cuda_bf16.h>
#include <cuda_fp16.h>
#include <cstdint>

#define N_NODES 100000
#define N_EDGES 1600000
#define N_PAIRS 200000
#define CH 128

typedef unsigned int u32;
typedef unsigned long long u64;

// ---------------- scratch (static device globals; no allocation) -------------
__device__ int   g_cnt[N_NODES];
__device__ int   g_rowptr[N_NODES + 1];
__device__ int   g_cursor[N_NODES];
__device__ int2  g_csr[N_EDGES];

__device__ __align__(16) __half g_x16[(size_t)N_NODES * CH];  // 25.6 MB
__device__ __align__(16) __half g_h16[(size_t)N_NODES * CH];  // 25.6 MB
__device__ __align__(16) __half g_a16[(size_t)N_NODES * CH];  // 25.6 MB (agg, fp16)
__device__ float g_z[(size_t)N_NODES * CH];                   // 51.2 MB fp32
// weight image: 2 layers x 4 k-chunks x 16KB fp16 (swizzled) = 128 KB
__device__ __align__(16) u32 g_Bimg[32768];

// ---------------- PTX helpers (all plain sm_80+ ISA) -------------------------
__device__ __forceinline__ u32 smem_u32(const void* p) {
    u32 a;
    asm("{ .reg .u64 t; cvta.to.shared.u64 t, %1; cvt.u32.u64 %0, t; }" : "=r"(a) : "l"(p));
    return a;
}

__device__ __forceinline__ void ldsm_x4(u32& r0, u32& r1, u32& r2, u32& r3, u32 addr) {
    asm volatile("ldmatrix.sync.aligned.m8n8.x4.shared.b16 {%0,%1,%2,%3}, [%4];"
                 : "=r"(r0), "=r"(r1), "=r"(r2), "=r"(r3) : "r"(addr));
}

__device__ __forceinline__ void mma_f16(float* c, const u32* a, const u32* b) {
    asm volatile(
        "mma.sync.aligned.m16n8k16.row.col.f32.f16.f16.f32 "
        "{%0,%1,%2,%3}, {%4,%5,%6,%7}, {%8,%9}, {%0,%1,%2,%3};"
        : "+f"(c[0]), "+f"(c[1]), "+f"(c[2]), "+f"(c[3])
        : "r"(a[0]), "r"(a[1]), "r"(a[2]), "r"(a[3]), "r"(b[0]), "r"(b[1]));
}

__device__ __forceinline__ void cpa16(u32 dst, const void* src, bool pred) {
    int sz = pred ? 16 : 0;
    asm volatile("cp.async.cg.shared.global [%0], [%1], 16, %2;"
                 :: "r"(dst), "l"(src), "r"(sz) : "memory");
}
#define CPA_COMMIT()  asm volatile("cp.async.commit_group;" ::: "memory")
#define CPA_WAIT(n)   asm volatile("cp.async.wait_group %0;" :: "n"(n) : "memory")

// fp16 pack/unpack
__device__ __forceinline__ u32 pack_h2(float a, float b) {
    __half2 h = __floats2half2_rn(a, b);
    return *reinterpret_cast<u32*>(&h);
}
__device__ __forceinline__ float2 unp_h2(u32 v) {
    __half2 h = *reinterpret_cast<__half2*>(&v);
    return __half22float2(h);
}

// ---------------- CSR build --------------------------------------------------
__global__ void k_zero() {
    int i = blockIdx.x * blockDim.x + threadIdx.x;
    if (i < N_NODES) g_cnt[i] = 0;
}

// fused: edge-dst histogram + x -> fp16 (both exactly 1.6M threads)
__global__ void k_hist_cvt(const int* __restrict__ ei, const float* __restrict__ x) {
    int gid = blockIdx.x * blockDim.x + threadIdx.x;
    if (gid >= N_EDGES) return;
    atomicAdd(&g_cnt[ei[N_EDGES + gid]], 1);
    // convert 8 channels: N_EDGES == N_NODES*16 exactly
    const float4* x4 = reinterpret_cast<const float4*>(x);
    float4 a = x4[gid * 2];
    float4 b = x4[gid * 2 + 1];
    uint4 o = make_uint4(pack_h2(a.x, a.y), pack_h2(a.z, a.w),
                         pack_h2(b.x, b.y), pack_h2(b.z, b.w));
    reinterpret_cast<uint4*>(g_x16)[gid] = o;
}

__global__ void k_scan() {
    __shared__ int sm[1024];
    const int CHUNK = (N_NODES + 1023) / 1024;
    int t = threadIdx.x;
    int beg = t * CHUNK;
    int end = beg + CHUNK; if (end > N_NODES) end = N_NODES;
    int s = 0;
    for (int i = beg; i < end && i < N_NODES; i++) s += g_cnt[i];
    sm[t] = s;
    __syncthreads();
    for (int off = 1; off < 1024; off <<= 1) {
        int v = (t >= off) ? sm[t - off] : 0;
        __syncthreads();
        sm[t] += v;
        __syncthreads();
    }
    int run = sm[t] - s;
    for (int i = beg; i < end && i < N_NODES; i++) {
        int c = g_cnt[i];
        g_rowptr[i] = run;
        g_cursor[i] = run;
        run += c;
    }
    if (t == 1023) g_rowptr[N_NODES] = sm[1023];
}

// fused: CSR scatter (all 1.6M threads) + fp16 weight swizzle (first 64K)
__global__ void k_scatter_prep(const int* __restrict__ ei, const float* __restrict__ ew,
                               const float* __restrict__ w1_rel, const float* __restrict__ w1_root,
                               const float* __restrict__ w2_rel, const float* __restrict__ w2_root) {
    int e = blockIdx.x * blockDim.x + threadIdx.x;
    if (e < N_EDGES) {
        int d = ei[N_EDGES + e];
        int p = atomicAdd(&g_cursor[d], 1);
        g_csr[p] = make_int2(ei[e], __float_as_int(ew[e]));
    }
    if (e < 65536) {
        int l = e >> 15;
        int r = e & 32767;
        int k = r >> 7;          // 0..255
        int n = r & 127;
        const float* W = (k < 128) ? (l ? w2_rel : w1_rel) : (l ? w2_root : w1_root);
        float v = W[(k & 127) * 128 + n];   // B[n][k] = W[k][n]
        int c  = k >> 6;
        int kk = k & 63;
        int u  = kk >> 3;
        int bi = (kk & 7) * 2;
        u32 phys = (u32)n * 128u + (u32)(((u ^ (n & 7)) << 4) | bi);
        u32 base = (u32)(l * 4 + c) * 16384u;
        unsigned short* B = reinterpret_cast<unsigned short*>(g_Bimg);
        __half hv = __float2half_rn(v);
        B[(base + phys) >> 1] = __half_as_ushort(hv);
    }
}

// ---------------- gather-side mean aggregation (fp16 gather, fp32 accum) -----
// warp per node (no intra-warp degree divergence), uint2 per lane, 4-edge unroll
// (R15 configuration — best measured)
__global__ void k_agg(int use_h) {
    int gid  = blockIdx.x * blockDim.x + threadIdx.x;
    int node = gid >> 5;
    if (node >= N_NODES) return;
    int lane = gid & 31;
    const uint2* feat = reinterpret_cast<const uint2*>(use_h ? g_h16 : g_x16);

    int beg = g_rowptr[node];
    int end = g_rowptr[node + 1];

    float ax = 0.f, ay = 0.f, az = 0.f, aw = 0.f;
    int e = beg;
    #pragma unroll 1
    for (; e + 4 <= end; e += 4) {
        int2 c0 = __ldg(&g_csr[e]);
        int2 c1 = __ldg(&g_csr[e + 1]);
        int2 c2 = __ldg(&g_csr[e + 2]);
        int2 c3 = __ldg(&g_csr[e + 3]);
        uint2 v0 = __ldg(feat + (size_t)c0.x * 32 + lane);
        uint2 v1 = __ldg(feat + (size_t)c1.x * 32 + lane);
        uint2 v2 = __ldg(feat + (size_t)c2.x * 32 + lane);
        uint2 v3 = __ldg(feat + (size_t)c3.x * 32 + lane);
        float w0 = __int_as_float(c0.y), w1 = __int_as_float(c1.y);
        float w2 = __int_as_float(c2.y), w3 = __int_as_float(c3.y);
        float2 a0 = unp_h2(v0.x), b0 = unp_h2(v0.y);
        float2 a1 = unp_h2(v1.x), b1 = unp_h2(v1.y);
        float2 a2 = unp_h2(v2.x), b2 = unp_h2(v2.y);
        float2 a3 = unp_h2(v3.x), b3 = unp_h2(v3.y);
        ax = fmaf(w0, a0.x, ax); ay = fmaf(w0, a0.y, ay);
        az = fmaf(w0, b0.x, az); aw = fmaf(w0, b0.y, aw);
        ax = fmaf(w1, a1.x, ax); ay = fmaf(w1, a1.y, ay);
        az = fmaf(w1, b1.x, az); aw = fmaf(w1, b1.y, aw);
        ax = fmaf(w2, a2.x, ax); ay = fmaf(w2, a2.y, ay);
        az = fmaf(w2, b2.x, az); aw = fmaf(w2, b2.y, aw);
        ax = fmaf(w3, a3.x, ax); ay = fmaf(w3, a3.y, ay);
        az = fmaf(w3, b3.x, az); aw = fmaf(w3, b3.y, aw);
    }
    #pragma unroll 1
    for (; e < end; e++) {
        int2 c0 = __ldg(&g_csr[e]);
        float w0 = __int_as_float(c0.y);
        uint2 v0 = __ldg(feat + (size_t)c0.x * 32 + lane);
        float2 a0 = unp_h2(v0.x), b0 = unp_h2(v0.y);
        ax = fmaf(w0, a0.x, ax); ay = fmaf(w0, a0.y, ay);
        az = fmaf(w0, b0.x, az); aw = fmaf(w0, b0.y, aw);
    }
    float inv = 1.0f / fmaxf((float)(end - beg), 1.0f);
    uint2 o = make_uint2(pack_h2(ax * inv, ay * inv), pack_h2(az * inv, aw * inv));
    reinterpret_cast<uint2*>(g_a16)[(size_t)node * 32 + lane] = o;
}

// ---------------- mma.sync fp16 GEMM -----------------------------------------
// out[m,0:128] = act([agg | other][m,0:256] @ W[256,128] + bias)
// All operands are fp16 -> plain f16.f16.f32 MMA, no precision splitting.
// smem per chunk: A 16K | B 16K = 32 KB; fp32 stage (128x132 = 67.6 KB)
// overlays it after compute. 2 CTAs/SM.
#define GM_SMEM 67584

__global__ __launch_bounds__(256, 2) void k_gemm_mma(const float* __restrict__ bias, int layer)
{
    extern __shared__ char smem[];
    const u32 sb = smem_u32(smem);
    const int tid  = threadIdx.x;
    const int lane = tid & 31;
    const int wid  = tid >> 5;
    const int m0   = blockIdx.x * 128;

    const uint4* agg16   = reinterpret_cast<const uint4*>(g_a16);
    const uint4* other16 = reinterpret_cast<const uint4*>(layer ? g_h16 : g_x16);
    const uint4* Bimg = reinterpret_cast<const uint4*>(g_Bimg) + (size_t)layer * 4096;

    const int mbase = (wid >> 2) * 64;
    const int ntb   = (wid & 3) * 4;        // n-tile base (n8 units)

    float acc[4][4][4];
    #pragma unroll
    for (int a = 0; a < 4; a++)
        #pragma unroll
        for (int b = 0; b < 4; b++)
            #pragma unroll
            for (int d = 0; d < 4; d++) acc[a][b][d] = 0.f;

    #pragma unroll 1
    for (int c = 0; c < 4; c++) {
        // ---- B fp16 tile via cp.async (pre-swizzled) ----
        const uint4* bsrc = Bimg + (size_t)c * 1024;   // 16 KB
        #pragma unroll
        for (int i = 0; i < 4; i++) {
            int e = i * 256 + tid;
            cpa16(sb + 16384u + (u32)e * 16u, bsrc + e, true);
        }
        CPA_COMMIT();

        // ---- A fp16 tile: straight swizzled copy ----
        {
            int half = c & 1;               // K cols [half*64, half*64+64)
            const uint4* src = (c >> 1) ? other16 : agg16;
            #pragma unroll
            for (int i = 0; i < 4; i++) {
                int t = i * 256 + tid;      // 0..1023 : 128 rows x 8 units
                int r = t >> 3, u = t & 7;
                int gm = m0 + r;
                uint4 raw = make_uint4(0, 0, 0, 0);
                if (gm < N_NODES)
                    raw = __ldg(src + (size_t)gm * 16 + half * 8 + u);
                u32 off = (u32)(r * 128 + ((u ^ (r & 7)) << 4));
                *reinterpret_cast<uint4*>(smem + off) = raw;
            }
        }

        CPA_WAIT(0);
        __syncthreads();

        #pragma unroll
        for (int ks = 0; ks < 4; ks++) {
            u32 ah[4][4], bh[4][2];
            #pragma unroll
            for (int mt = 0; mt < 4; mt++) {
                int row = mbase + mt * 16 + (lane & 15);
                int u   = 2 * ks + (lane >> 4);
                u32 off = (u32)(row * 128 + ((u ^ (row & 7)) << 4));
                ldsm_x4(ah[mt][0], ah[mt][1], ah[mt][2], ah[mt][3], sb + off);
            }
            #pragma unroll
            for (int pr = 0; pr < 2; pr++) {
                int g  = lane >> 3;
                int nt = ntb + pr * 2 + (g >> 1);
                int rn = nt * 8 + (lane & 7);
                int u  = 2 * ks + (g & 1);
                u32 off = (u32)(rn * 128 + ((u ^ (rn & 7)) << 4));
                ldsm_x4(bh[pr*2][0], bh[pr*2][1], bh[pr*2+1][0], bh[pr*2+1][1], sb + 16384u + off);
            }
            #pragma unroll
            for (int mt = 0; mt < 4; mt++)
                #pragma unroll
                for (int nt = 0; nt < 4; nt++)
                    mma_f16(acc[mt][nt], ah[mt], bh[nt]);
        }
        __syncthreads();
    }

    // ---- stage accumulators to smem (overlays buffers) ----
    float* stage = reinterpret_cast<float*>(smem);
    #pragma unroll
    for (int mt = 0; mt < 4; mt++)
        #pragma unroll
        for (int nt = 0; nt < 4; nt++) {
            int row = mbase + mt * 16 + (lane >> 2);
            int col = (wid & 3) * 32 + nt * 8 + (lane & 3) * 2;
            stage[row * 132 + col]           = acc[mt][nt][0];
            stage[row * 132 + col + 1]       = acc[mt][nt][1];
            stage[(row + 8) * 132 + col]     = acc[mt][nt][2];
            stage[(row + 8) * 132 + col + 1] = acc[mt][nt][3];
        }
    __syncthreads();

    // ---- bias / act / store ----
    if (layer == 0) {
        // h -> fp16 (+ReLU), packed half2 stores
        u32* oh = reinterpret_cast<u32*>(g_h16);
        #pragma unroll 4
        for (int i = 0; i < 32; i++) {
            int p = i * 256 + tid;          // pair index: 8192 pairs
            int m = p >> 6, c2 = (p & 63) * 2;
            int gm = m0 + m;
            if (gm >= N_NODES) continue;
            float v0 = stage[m * 132 + c2]     + __ldg(&bias[c2]);
            float v1 = stage[m * 132 + c2 + 1] + __ldg(&bias[c2 + 1]);
            v0 = fmaxf(v0, 0.f);
            v1 = fmaxf(v1, 0.f);
            oh[(size_t)gm * 64 + (c2 >> 1)] = pack_h2(v0, v1);
        }
    } else {
        #pragma unroll 4
        for (int i = 0; i < 64; i++) {
            int p = i * 256 + tid;          // element index: 16384
            int m = p >> 7, cc = p & 127;
            int gm = m0 + m;
            if (gm >= N_NODES) continue;
            g_z[(size_t)gm * CH + cc] = stage[m * 132 + cc] + __ldg(&bias[cc]);
        }
    }
}

// ---------------- decode: warp per candidate pair (fp32 z) -------------------
__global__ void k_decode(const int* __restrict__ eli, float* __restrict__ out) {
    int gid = blockIdx.x * blockDim.x + threadIdx.x;
    int p = gid >> 5;
    if (p >= N_PAIRS) return;
    int lane = gid & 31;
    int a = eli[p];
    int b = eli[N_PAIRS + p];
    float4 va = *reinterpret_cast<const float4*>(&g_z[(size_t)a * CH + lane * 4]);
    float4 vb = *reinterpret_cast<const float4*>(&g_z[(size_t)b * CH + lane * 4]);
    float s = va.x * vb.x + va.y * vb.y + va.z * vb.z + va.w * vb.w;
    #pragma unroll
    for (int off = 16; off > 0; off >>= 1) s += __shfl_xor_sync(0xFFFFFFFFu, s, off);
    if (lane == 0) out[p] = s * 0.08838834764831845f;   // 1/sqrt(128)
}

// ---------------- launch -----------------------------------------------------
extern "C" void kernel_launch(void* const* d_in, const int* in_sizes, int n_in,
                              void* d_out, int out_size) {
    const float* x       = (const float*)d_in[0];
    const int*   ei      = (const int*)  d_in[1];
    const float* ew      = (const float*)d_in[2];
    const int*   eli     = (const int*)  d_in[3];
    const float* w1_rel  = (const float*)d_in[4];
    const float* b1      = (const float*)d_in[5];
    const float* w1_root = (const float*)d_in[6];
    const float* w2_rel  = (const float*)d_in[7];
    const float* b2      = (const float*)d_in[8];
    const float* w2_root = (const float*)d_in[9];
    float* out = (float*)d_out;

    cudaFuncSetAttribute(k_gemm_mma, cudaFuncAttributeMaxDynamicSharedMemorySize, GM_SMEM);

    // CSR build + operand prep (x->fp16 fused with hist, weights with scatter)
    k_zero        <<<(N_NODES + 255) / 256, 256>>>();
    k_hist_cvt    <<<(N_EDGES + 255) / 256, 256>>>(ei, x);
    k_scan        <<<1, 1024>>>();
    k_scatter_prep<<<(N_EDGES + 255) / 256, 256>>>(ei, ew, w1_rel, w1_root, w2_rel, w2_root);

    const int aggBlocks  = (N_NODES * 32 + 255) / 256;
    const int gemmBlocks = (N_NODES + 127) / 128;

    // layer 1: h = relu([agg(x) | x] @ [W1_rel; W1_root] + b1)  (fp16 h)
    k_agg     <<<aggBlocks, 256>>>(0);
    k_gemm_mma<<<gemmBlocks, 256, GM_SMEM>>>(b1, 0);

    // layer 2: z = [agg(h) | h] @ [W2_rel; W2_root] + b2  (fp32 z)
    k_agg     <<<aggBlocks, 256>>>(1);
    k_gemm_mma<<<gemmBlocks, 256, GM_SMEM>>>(b2, 1);

    // decode
    k_decode<<<(N_PAIRS * 32 + 255) / 256, 256>>>(eli, out);
}